// round 6
// baseline (speedup 1.0000x reference)
#include <cuda_runtime.h>
#include <math.h>
#include <stdint.h>

#define Bsz 32
#define Ssz 512
#define Tsz 180
#define Dsz 512
#define Fsz 2048
#define Lsz 6
#define Hsz 8
#define DHsz 64

// ---------------- scratch ----------------
__device__ float g_h   [Bsz*Ssz*Dsz];
__device__ float g_tmp [Bsz*Ssz*Dsz];
__device__ float g_q   [Bsz*Ssz*Dsz];
__device__ float g_k   [Bsz*Ssz*Dsz];
__device__ float g_v   [Bsz*Ssz*Dsz];
__device__ float g_ffn [Bsz*Ssz*Fsz];
__device__ float g_d   [Bsz*Tsz*Dsz];
__device__ float g_dq  [Bsz*Tsz*Dsz];
__device__ float g_dtmp[Bsz*Tsz*Dsz];

// ---------------- helpers ----------------
__device__ __forceinline__ float warpSum(float v) {
    #pragma unroll
    for (int o = 16; o; o >>= 1) v += __shfl_xor_sync(0xffffffffu, v, o);
    return v;
}
__device__ __forceinline__ float warpMax(float v) {
    #pragma unroll
    for (int o = 16; o; o >>= 1) v = fmaxf(v, __shfl_xor_sync(0xffffffffu, v, o));
    return v;
}
__device__ __forceinline__ uint4 cvt_tf32x4(float4 v) {
    uint4 u;
    asm("cvt.rna.tf32.f32 %0, %1;" : "=r"(u.x) : "f"(v.x));
    asm("cvt.rna.tf32.f32 %0, %1;" : "=r"(u.y) : "f"(v.y));
    asm("cvt.rna.tf32.f32 %0, %1;" : "=r"(u.z) : "f"(v.z));
    asm("cvt.rna.tf32.f32 %0, %1;" : "=r"(u.w) : "f"(v.w));
    return u;
}
__device__ __forceinline__ float cvt_tf32(float v) {
    uint32_t u;
    asm("cvt.rna.tf32.f32 %0, %1;" : "=r"(u) : "f"(v));
    return __uint_as_float(u);
}
#define MMA_TF32(c, a, b) \
    asm volatile("mma.sync.aligned.m16n8k8.row.col.f32.tf32.tf32.f32 " \
        "{%0,%1,%2,%3}, {%4,%5,%6,%7}, {%8,%9}, {%0,%1,%2,%3};" \
        : "+f"((c)[0]), "+f"((c)[1]), "+f"((c)[2]), "+f"((c)[3]) \
        : "r"((a)[0]), "r"((a)[1]), "r"((a)[2]), "r"((a)[3]), \
          "r"((b)[0]), "r"((b)[1]))

// ---------------- fragment-native TF32 GEMM ----------------------------------------
// C[M,N] = A[M,K] @ B[K,N] + bias[N], opt ReLU. Tile 128x128, BK=32, 256 thr.
// Smem layouts are fragment-contiguous:
//   A: [kk][mb][lane*4 + reg]  (LDS.128 per (mt,kk) fragment)
//   B: [kk][nb][lane*2 + reg]  (LDS.64  per (nt,kk) fragment)
// where lane = (row%8)*4 + (k%4) for A / (n%8)*4 + (k%4) for B.
#define GSMEM (2 * 4096 * 2 * 4)   // 64KB: As[2][4096] + Bs[2][4096]

template<int KLO, int KHI>
__device__ __forceinline__ void mma_stage(
    const float* __restrict__ Ab, const float* __restrict__ Bb,
    int aF, int bF, float acc[4][4][4])
{
    #pragma unroll
    for (int kk = KLO; kk < KHI; kk++) {
        float4 af[4];
        float2 bf[4];
        #pragma unroll
        for (int mt = 0; mt < 4; mt++)
            af[mt] = *(const float4*)(Ab + kk * 1024 + mt * 128 + aF);
        #pragma unroll
        for (int nt = 0; nt < 4; nt++)
            bf[nt] = *(const float2*)(Bb + kk * 1024 + nt * 64 + bF);
        #pragma unroll
        for (int mt = 0; mt < 4; mt++)
            #pragma unroll
            for (int nt = 0; nt < 4; nt++)
                MMA_TF32(acc[mt][nt], ((uint32_t*)&af[mt]), ((uint32_t*)&bf[nt]));
    }
}

__device__ __forceinline__ void stsA(float* __restrict__ Ab, const float4* a4,
                                     int aBase, int tsel)
{
    #pragma unroll
    for (int p = 0; p < 4; p++) {
        uint4 u = cvt_tf32x4(a4[p]);
        float* dst = Ab + aBase + (tsel * 2 + (p >> 1)) * 1024 + (p & 1) * 2;
        dst[0]  = __uint_as_float(u.x);
        dst[4]  = __uint_as_float(u.y);
        dst[8]  = __uint_as_float(u.z);
        dst[12] = __uint_as_float(u.w);
    }
}
__device__ __forceinline__ void stsB(float* __restrict__ Bb, const float4* b4,
                                     int bBase)
{
    #pragma unroll
    for (int p = 0; p < 4; p++) {
        uint4 u = cvt_tf32x4(b4[p]);
        float* dst = Bb + bBase + p * 256;
        dst[0]  = __uint_as_float(u.x);
        dst[8]  = __uint_as_float(u.y);
        dst[16] = __uint_as_float(u.z);
        dst[24] = __uint_as_float(u.w);
    }
}

__global__ __launch_bounds__(256, 2) void gemm_tf32(
    const float* __restrict__ A, const float* __restrict__ B,
    const float* __restrict__ bias, float* __restrict__ C,
    int M, int N, int K, int doRelu)
{
    extern __shared__ float smg[];
    float* As = smg;            // [2][4096]
    float* Bs = smg + 8192;     // [2][4096]

    const int tid = threadIdx.x, lane = tid & 31, warp = tid >> 5;
    const int bm = blockIdx.y << 7, bn = blockIdx.x << 7;

    // ---- staging indices ----
    const int ar = tid >> 1;              // A row 0..127
    const int ac = (tid & 1) << 4;        // A col base 0/16
    const int tsel = tid & 1;
    const int aBase = ((ar >> 4) << 7) + ((ar & 7) << 4) + ((ar >> 3) & 1);
    const int bk = tid >> 3;              // B k-row 0..31
    const int bBase = ((bk >> 3) << 10) + (((tid & 7) >> 1) << 6) + ((tid & 1) << 5)
                    + ((bk & 3) << 1) + ((bk >> 2) & 1);

    const float* Ag = A + (size_t)(bm + ar) * K + ac;
    const float* Bg = B + (size_t)bk * N + bn + ((tid & 7) << 2);

    // ---- fragment read bases ----
    const int aF = ((warp >> 2) * 4) * 128 + lane * 4;
    const int bF = ((warp & 3) * 4) * 64 + lane * 2;

    float acc[4][4][4] = {};
    float4 a4[4], b4[4];

    // prologue: stage chunk 0
    #pragma unroll
    for (int p = 0; p < 4; p++) a4[p] = *(const float4*)(Ag + p * 4);
    #pragma unroll
    for (int p = 0; p < 4; p++) b4[p] = *(const float4*)(Bg + p * 32);
    stsA(As, a4, aBase, tsel);
    stsB(Bs, b4, bBase);
    __syncthreads();

    const int nc = K >> 5;
    int buf = 0;
    for (int c = 1; c < nc; c++) {
        const float* Agc = Ag + c * 32;
        const float* Bgc = Bg + (size_t)c * 32 * N;
        #pragma unroll
        for (int p = 0; p < 4; p++) a4[p] = *(const float4*)(Agc + p * 4);
        #pragma unroll
        for (int p = 0; p < 4; p++) b4[p] = *(const float4*)(Bgc + p * 32);

        mma_stage<0, 2>(As + buf * 4096, Bs + buf * 4096, aF, bF, acc);
        stsA(As + (buf ^ 1) * 4096, a4, aBase, tsel);
        mma_stage<2, 4>(As + buf * 4096, Bs + buf * 4096, aF, bF, acc);
        stsB(Bs + (buf ^ 1) * 4096, b4, bBase);
        __syncthreads();
        buf ^= 1;
    }
    mma_stage<0, 4>(As + buf * 4096, Bs + buf * 4096, aF, bF, acc);

    // ---- epilogue: bias (+relu), float2 stores ----
    const int g = lane >> 2, t4 = lane & 3;
    const int wm = (warp >> 2) << 6, wn = (warp & 3) << 5;
    #pragma unroll
    for (int mt = 0; mt < 4; mt++) {
        const int gm = bm + wm + mt * 16 + g;
        #pragma unroll
        for (int nt = 0; nt < 4; nt++) {
            const int gn = bn + wn + nt * 8 + (t4 << 1);
            const float b0v = bias[gn], b1v = bias[gn + 1];
            float2 o0 = make_float2(acc[mt][nt][0] + b0v, acc[mt][nt][1] + b1v);
            float2 o1 = make_float2(acc[mt][nt][2] + b0v, acc[mt][nt][3] + b1v);
            if (doRelu) {
                o0.x = fmaxf(o0.x, 0.f); o0.y = fmaxf(o0.y, 0.f);
                o1.x = fmaxf(o1.x, 0.f); o1.y = fmaxf(o1.y, 0.f);
            }
            *(float2*)(C + (size_t)gm * N + gn)       = o0;
            *(float2*)(C + (size_t)(gm + 8) * N + gn) = o1;
        }
    }
}

// ---------------- tensor-core flash attention (unchanged, proven) ------------------
#define ATT_SMEM ((4 * 64 * 68 + 192) * 4)
__global__ __launch_bounds__(256) void attn_mma(
    const float* __restrict__ Q, const float* __restrict__ K,
    const float* __restrict__ V, float* __restrict__ O,
    int Sq, int Sk, int causal)
{
    extern __shared__ float sm[];
    float* Qs = sm;
    float* Ks = sm + 4352;
    float* Vs = sm + 8704;
    float* Ss = sm + 13056;
    float* m_row = sm + 17408;
    float* s_row = m_row + 64;
    float* f_row = s_row + 64;

    const int tid = threadIdx.x, lane = tid & 31, w = tid >> 5;
    const int wm = w & 3, wn = w >> 2;
    const int g = lane >> 2, t4 = lane & 3;
    const int qbase = blockIdx.x * 64;
    const int h = blockIdx.y, b = blockIdx.z;
    const size_t hoff = (size_t)h * DHsz;

    #pragma unroll
    for (int p = 0; p < 4; p++) {
        const int row = (tid >> 4) + p * 16;
        const int d4  = (tid & 15) << 2;
        const int qg  = qbase + row;
        float4 v4 = (qg < Sq)
            ? *(const float4*)(Q + (size_t)(b * Sq + qg) * Dsz + hoff + d4)
            : make_float4(0.f, 0.f, 0.f, 0.f);
        *(uint4*)&Qs[row * 68 + d4] = cvt_tf32x4(v4);
    }
    if (tid < 64) { m_row[tid] = -1e30f; s_row[tid] = 0.f; }
    __syncthreads();

    const int qr = wm * 16 + g;
    uint32_t qf[8][4];
    #pragma unroll
    for (int kk = 0; kk < 8; kk++) {
        qf[kk][0] = __float_as_uint(Qs[qr * 68 + kk * 8 + t4]);
        qf[kk][1] = __float_as_uint(Qs[(qr + 8) * 68 + kk * 8 + t4]);
        qf[kk][2] = __float_as_uint(Qs[qr * 68 + kk * 8 + t4 + 4]);
        qf[kk][3] = __float_as_uint(Qs[(qr + 8) * 68 + kk * 8 + t4 + 4]);
    }

    float acc_o[4][4] = {};
    const int qend = qbase + 63;

    for (int c0 = 0; c0 < Sk; c0 += 64) {
        if (causal && c0 > qend) break;
        #pragma unroll
        for (int p = 0; p < 4; p++) {
            const int row = (tid >> 4) + p * 16;
            const int d4  = (tid & 15) << 2;
            const int kg  = c0 + row;
            float4 kv = make_float4(0.f, 0.f, 0.f, 0.f), vv = kv;
            if (kg < Sk) {
                kv = *(const float4*)(K + (size_t)(b * Sk + kg) * Dsz + hoff + d4);
                vv = *(const float4*)(V + (size_t)(b * Sk + kg) * Dsz + hoff + d4);
            }
            *(uint4*)&Ks[row * 68 + d4] = cvt_tf32x4(kv);
            *(uint4*)&Vs[row * 68 + d4] = cvt_tf32x4(vv);
        }
        __syncthreads();

        float acc_s[4][4] = {};
        #pragma unroll
        for (int kk = 0; kk < 8; kk++) {
            #pragma unroll
            for (int nt = 0; nt < 4; nt++) {
                const int key = wn * 32 + nt * 8 + g;
                uint32_t bf[2];
                bf[0] = __float_as_uint(Ks[key * 68 + kk * 8 + t4]);
                bf[1] = __float_as_uint(Ks[key * 68 + kk * 8 + t4 + 4]);
                MMA_TF32(acc_s[nt], qf[kk], bf);
            }
        }
        {
            const int qg0 = qbase + qr, qg1 = qg0 + 8;
            #pragma unroll
            for (int nt = 0; nt < 4; nt++) {
                const int cl = wn * 32 + nt * 8 + (t4 << 1);
                const int kg = c0 + cl;
                float s00 = acc_s[nt][0] * 0.125f, s01 = acc_s[nt][1] * 0.125f;
                float s10 = acc_s[nt][2] * 0.125f, s11 = acc_s[nt][3] * 0.125f;
                if (kg >= Sk || (causal && kg > qg0)) s00 = -1e30f;
                if (kg + 1 >= Sk || (causal && kg + 1 > qg0)) s01 = -1e30f;
                if (kg >= Sk || (causal && kg > qg1)) s10 = -1e30f;
                if (kg + 1 >= Sk || (causal && kg + 1 > qg1)) s11 = -1e30f;
                Ss[qr * 68 + cl] = s00;        Ss[qr * 68 + cl + 1] = s01;
                Ss[(qr + 8) * 68 + cl] = s10;  Ss[(qr + 8) * 68 + cl + 1] = s11;
            }
        }
        __syncthreads();

        #pragma unroll
        for (int rr = 0; rr < 8; rr++) {
            const int r = w * 8 + rr;
            float s0v = Ss[r * 68 + lane];
            float s1v = Ss[r * 68 + lane + 32];
            const float mx = warpMax(fmaxf(s0v, s1v));
            const float mold = m_row[r];
            const float mnew = fmaxf(mold, mx);
            float p0 = __expf(s0v - mnew);
            float p1 = __expf(s1v - mnew);
            const float sum = warpSum(p0 + p1);
            Ss[r * 68 + lane]      = cvt_tf32(p0);
            Ss[r * 68 + lane + 32] = cvt_tf32(p1);
            if (lane == 0) {
                const float f = __expf(mold - mnew);
                f_row[r] = f;
                s_row[r] = s_row[r] * f + sum;
                m_row[r] = mnew;
            }
        }
        __syncthreads();

        {
            const float f0 = f_row[qr], f1 = f_row[qr + 8];
            #pragma unroll
            for (int nt = 0; nt < 4; nt++) {
                acc_o[nt][0] *= f0; acc_o[nt][1] *= f0;
                acc_o[nt][2] *= f1; acc_o[nt][3] *= f1;
            }
        }
        #pragma unroll
        for (int kk = 0; kk < 8; kk++) {
            uint32_t af[4];
            af[0] = __float_as_uint(Ss[qr * 68 + kk * 8 + t4]);
            af[1] = __float_as_uint(Ss[(qr + 8) * 68 + kk * 8 + t4]);
            af[2] = __float_as_uint(Ss[qr * 68 + kk * 8 + t4 + 4]);
            af[3] = __float_as_uint(Ss[(qr + 8) * 68 + kk * 8 + t4 + 4]);
            #pragma unroll
            for (int nt = 0; nt < 4; nt++) {
                const int dcol = wn * 32 + nt * 8 + g;
                uint32_t bf[2];
                bf[0] = __float_as_uint(Vs[(kk * 8 + t4) * 68 + dcol]);
                bf[1] = __float_as_uint(Vs[(kk * 8 + t4 + 4) * 68 + dcol]);
                MMA_TF32(acc_o[nt], af, bf);
            }
        }
        __syncthreads();
    }

    const float inv0 = 1.f / s_row[qr];
    const float inv1 = 1.f / s_row[qr + 8];
    const int qg0 = qbase + qr, qg1 = qg0 + 8;
    #pragma unroll
    for (int nt = 0; nt < 4; nt++) {
        const int dcol = wn * 32 + nt * 8 + (t4 << 1);
        if (qg0 < Sq)
            *(float2*)(O + (size_t)(b * Sq + qg0) * Dsz + hoff + dcol) =
                make_float2(acc_o[nt][0] * inv0, acc_o[nt][1] * inv0);
        if (qg1 < Sq)
            *(float2*)(O + (size_t)(b * Sq + qg1) * Dsz + hoff + dcol) =
                make_float2(acc_o[nt][2] * inv1, acc_o[nt][3] * inv1);
    }
}

// ---------------- residual + LayerNorm ---------------------------------------------
__global__ __launch_bounds__(128) void add_ln_kernel(
    float* __restrict__ h, const float* __restrict__ r,
    const float* __restrict__ scale, const float* __restrict__ bias)
{
    const int row = blockIdx.x;
    const int tid = threadIdx.x;
    const int lane = tid & 31, warp = tid >> 5;
    float* hp = h + (size_t)row * Dsz;
    const float* rp = r + (size_t)row * Dsz;

    float4 hv = *(const float4*)(hp + tid * 4);
    float4 rv = *(const float4*)(rp + tid * 4);
    float v0 = hv.x + rv.x, v1 = hv.y + rv.y, v2 = hv.z + rv.z, v3 = hv.w + rv.w;

    float sum = v0 + v1 + v2 + v3;
    float sq  = v0*v0 + v1*v1 + v2*v2 + v3*v3;
    sum = warpSum(sum); sq = warpSum(sq);

    __shared__ float s1[4], s2[4];
    if (lane == 0) { s1[warp] = sum; s2[warp] = sq; }
    __syncthreads();
    sum = s1[0] + s1[1] + s1[2] + s1[3];
    sq  = s2[0] + s2[1] + s2[2] + s2[3];

    const float mu = sum * (1.f / Dsz);
    const float var = sq * (1.f / Dsz) - mu * mu;
    const float rs = rsqrtf(var + 1e-5f);

    float4 sc4 = *(const float4*)(scale + tid * 4);
    float4 bi4 = *(const float4*)(bias + tid * 4);
    float4 o;
    o.x = (v0 - mu) * rs * sc4.x + bi4.x;
    o.y = (v1 - mu) * rs * sc4.y + bi4.y;
    o.z = (v2 - mu) * rs * sc4.z + bi4.z;
    o.w = (v3 - mu) * rs * sc4.w + bi4.w;
    *(float4*)(hp + tid * 4) = o;
}

// ---------------- embeddings --------------------------------------------------------
__device__ __forceinline__ float pos_enc(int pos, int d) {
    const int i2 = d & ~1;
    const float freq = expf(-(float)i2 * (9.210340371976184f / 512.f));
    const float ang = (float)pos * freq;
    return (d & 1) ? cosf(ang) : sinf(ang);
}
__global__ __launch_bounds__(512) void embed_src_kernel(
    const float* __restrict__ x, const float* __restrict__ w,
    const float* __restrict__ b, float* __restrict__ h)
{
    const int token = blockIdx.x;
    const int d = threadIdx.x;
    const int s = token % Ssz;
    const float x0 = x[token * 2 + 0], x1 = x[token * 2 + 1];
    h[(size_t)token * Dsz + d] = x0 * w[d] + x1 * w[Dsz + d] + b[d] + pos_enc(s, d);
}
__global__ __launch_bounds__(512) void embed_tgt_kernel(
    const float* __restrict__ y, const float* __restrict__ w,
    const float* __restrict__ b, float* __restrict__ dd)
{
    const int token = blockIdx.x;
    const int d = threadIdx.x;
    const int bb = token / Tsz, t = token % Tsz;
    const float val = (t == 0) ? 0.f : y[bb * Tsz + (t - 1)];
    dd[(size_t)token * Dsz + d] = val * w[d] + b[d] + pos_enc(t, d);
}

// ---------------- final projection ---------------------------------------------------
__global__ __launch_bounds__(128) void out_proj_kernel(
    const float* __restrict__ dd, const float* __restrict__ w,
    const float* __restrict__ b, float* __restrict__ out)
{
    const int token = blockIdx.x;
    const int tid = threadIdx.x;
    const int lane = tid & 31, warp = tid >> 5;
    float s = 0.f;
    for (int i = tid; i < Dsz; i += 128)
        s += dd[(size_t)token * Dsz + i] * w[i];
    s = warpSum(s);
    __shared__ float smr[4];
    if (lane == 0) smr[warp] = s;
    __syncthreads();
    if (tid == 0) out[token] = smr[0] + smr[1] + smr[2] + smr[3] + b[0];
}

// ---------------- host orchestration -------------------------------------------------
extern "C" void kernel_launch(void* const* d_in, const int* in_sizes, int n_in,
                              void* d_out, int out_size)
{
    const float* x          = (const float*)d_in[0];
    const float* y          = (const float*)d_in[1];
    const float* src_w      = (const float*)d_in[2];
    const float* src_b      = (const float*)d_in[3];
    const float* tgt_w      = (const float*)d_in[4];
    const float* tgt_b      = (const float*)d_in[5];
    const float* enc_attn_w = (const float*)d_in[6];
    const float* enc_attn_b = (const float*)d_in[7];
    const float* enc_ffn_w1 = (const float*)d_in[8];
    const float* enc_ffn_b1 = (const float*)d_in[9];
    const float* enc_ffn_w2 = (const float*)d_in[10];
    const float* enc_ffn_b2 = (const float*)d_in[11];
    const float* enc_ln_s   = (const float*)d_in[12];
    const float* enc_ln_b   = (const float*)d_in[13];
    const float* dec_self_w = (const float*)d_in[14];
    const float* dec_self_b = (const float*)d_in[15];
    const float* dec_cross_w= (const float*)d_in[16];
    const float* dec_cross_b= (const float*)d_in[17];
    const float* dec_ffn_w1 = (const float*)d_in[18];
    const float* dec_ffn_b1 = (const float*)d_in[19];
    const float* dec_ffn_w2 = (const float*)d_in[20];
    const float* dec_ffn_b2 = (const float*)d_in[21];
    const float* dec_ln_s   = (const float*)d_in[22];
    const float* dec_ln_b   = (const float*)d_in[23];
    const float* out_w      = (const float*)d_in[24];
    const float* out_b      = (const float*)d_in[25];

    float *h, *tmp, *q, *k, *v, *ffn, *dd, *dq, *dtmp;
    cudaGetSymbolAddress((void**)&h,    g_h);
    cudaGetSymbolAddress((void**)&tmp,  g_tmp);
    cudaGetSymbolAddress((void**)&q,    g_q);
    cudaGetSymbolAddress((void**)&k,    g_k);
    cudaGetSymbolAddress((void**)&v,    g_v);
    cudaGetSymbolAddress((void**)&ffn,  g_ffn);
    cudaGetSymbolAddress((void**)&dd,   g_d);
    cudaGetSymbolAddress((void**)&dq,   g_dq);
    cudaGetSymbolAddress((void**)&dtmp, g_dtmp);

    const int Me = Bsz * Ssz;   // 16384
    const int Md = Bsz * Tsz;   // 5760
    const size_t DD = (size_t)Dsz * Dsz;

    cudaFuncSetAttribute(attn_mma, cudaFuncAttributeMaxDynamicSharedMemorySize, ATT_SMEM);
    cudaFuncSetAttribute(gemm_tf32, cudaFuncAttributeMaxDynamicSharedMemorySize, GSMEM);
    const int qtE = Ssz / 64;                 // 8
    const int qtD = (Tsz + 63) / 64;          // 3

    dim3 blk(256);
    dim3 gE_D(Dsz / 128, Me / 128);
    dim3 gE_F(Fsz / 128, Me / 128);
    dim3 gD_D(Dsz / 128, Md / 128);
    dim3 gD_F(Fsz / 128, Md / 128);

    // ===== encoder =====
    embed_src_kernel<<<Me, 512>>>(x, src_w, src_b, h);
    for (int l = 0; l < Lsz; l++) {
        const float* w  = enc_attn_w + (size_t)l * 4 * DD;
        const float* wb = enc_attn_b + (size_t)l * 4 * Dsz;
        gemm_tf32<<<gE_D, blk, GSMEM>>>(h, w,          wb,          q, Me, Dsz, Dsz, 0);
        gemm_tf32<<<gE_D, blk, GSMEM>>>(h, w + DD,     wb + Dsz,    k, Me, Dsz, Dsz, 0);
        gemm_tf32<<<gE_D, blk, GSMEM>>>(h, w + 2*DD,   wb + 2*Dsz,  v, Me, Dsz, Dsz, 0);
        attn_mma<<<dim3(qtE, Hsz, Bsz), 256, ATT_SMEM>>>(q, k, v, tmp, Ssz, Ssz, 0);
        gemm_tf32<<<gE_D, blk, GSMEM>>>(tmp, w + 3*DD, wb + 3*Dsz,  q, Me, Dsz, Dsz, 0);
        add_ln_kernel<<<Me, 128>>>(h, q, enc_ln_s + (size_t)(l*2)*Dsz,
                                         enc_ln_b + (size_t)(l*2)*Dsz);
        gemm_tf32<<<gE_F, blk, GSMEM>>>(h, enc_ffn_w1 + (size_t)l*Dsz*Fsz,
                                        enc_ffn_b1 + (size_t)l*Fsz, ffn, Me, Fsz, Dsz, 1);
        gemm_tf32<<<gE_D, blk, GSMEM>>>(ffn, enc_ffn_w2 + (size_t)l*Fsz*Dsz,
                                        enc_ffn_b2 + (size_t)l*Dsz, tmp, Me, Dsz, Fsz, 0);
        add_ln_kernel<<<Me, 128>>>(h, tmp, enc_ln_s + (size_t)(l*2+1)*Dsz,
                                           enc_ln_b + (size_t)(l*2+1)*Dsz);
    }

    // ===== decoder =====
    embed_tgt_kernel<<<Md, 512>>>(y, tgt_w, tgt_b, dd);
    for (int l = 0; l < Lsz; l++) {
        const float* w  = dec_self_w + (size_t)l * 4 * DD;
        const float* wb = dec_self_b + (size_t)l * 4 * Dsz;
        gemm_tf32<<<gD_D, blk, GSMEM>>>(dd, w,        wb,         dq, Md, Dsz, Dsz, 0);
        gemm_tf32<<<gD_D, blk, GSMEM>>>(dd, w + DD,   wb + Dsz,   k,  Md, Dsz, Dsz, 0);
        gemm_tf32<<<gD_D, blk, GSMEM>>>(dd, w + 2*DD, wb + 2*Dsz, v,  Md, Dsz, Dsz, 0);
        attn_mma<<<dim3(qtD, Hsz, Bsz), 256, ATT_SMEM>>>(dq, k, v, dtmp, Tsz, Tsz, 1);
        gemm_tf32<<<gD_D, blk, GSMEM>>>(dtmp, w + 3*DD, wb + 3*Dsz, dq, Md, Dsz, Dsz, 0);
        add_ln_kernel<<<Md, 128>>>(dd, dq, dec_ln_s + (size_t)(l*3)*Dsz,
                                           dec_ln_b + (size_t)(l*3)*Dsz);

        const float* cw  = dec_cross_w + (size_t)l * 4 * DD;
        const float* cwb = dec_cross_b + (size_t)l * 4 * Dsz;
        gemm_tf32<<<gD_D, blk, GSMEM>>>(dd, cw,        cwb,         dq, Md, Dsz, Dsz, 0);
        gemm_tf32<<<gE_D, blk, GSMEM>>>(h,  cw + DD,   cwb + Dsz,   k,  Me, Dsz, Dsz, 0);
        gemm_tf32<<<gE_D, blk, GSMEM>>>(h,  cw + 2*DD, cwb + 2*Dsz, v,  Me, Dsz, Dsz, 0);
        attn_mma<<<dim3(qtD, Hsz, Bsz), 256, ATT_SMEM>>>(dq, k, v, dtmp, Tsz, Ssz, 0);
        gemm_tf32<<<gD_D, blk, GSMEM>>>(dtmp, cw + 3*DD, cwb + 3*Dsz, dq, Md, Dsz, Dsz, 0);
        add_ln_kernel<<<Md, 128>>>(dd, dq, dec_ln_s + (size_t)(l*3+1)*Dsz,
                                           dec_ln_b + (size_t)(l*3+1)*Dsz);

        gemm_tf32<<<gD_F, blk, GSMEM>>>(dd, dec_ffn_w1 + (size_t)l*Dsz*Fsz,
                                        dec_ffn_b1 + (size_t)l*Fsz, ffn, Md, Fsz, Dsz, 1);
        gemm_tf32<<<gD_D, blk, GSMEM>>>(ffn, dec_ffn_w2 + (size_t)l*Fsz*Dsz,
                                        dec_ffn_b2 + (size_t)l*Dsz, dtmp, Md, Dsz, Fsz, 0);
        add_ln_kernel<<<Md, 128>>>(dd, dtmp, dec_ln_s + (size_t)(l*3+2)*Dsz,
                                             dec_ln_b + (size_t)(l*3+2)*Dsz);
    }

    out_proj_kernel<<<Md, 128>>>(dd, out_w, out_b, (float*)d_out);
}

// round 7
// speedup vs baseline: 1.7369x; 1.7369x over previous
#include <cuda_runtime.h>
#include <cuda_fp16.h>
#include <math.h>
#include <stdint.h>

#define Bsz 32
#define Ssz 512
#define Tsz 180
#define Dsz 512
#define Fsz 2048
#define Lsz 6
#define Hsz 8
#define DHsz 64

// ---------------- scratch ----------------
__device__ float g_h   [Bsz*Ssz*Dsz];
__device__ float g_tmp [Bsz*Ssz*Dsz];
__device__ float g_q   [Bsz*Ssz*Dsz];
__device__ float g_k   [Bsz*Ssz*Dsz];
__device__ float g_v   [Bsz*Ssz*Dsz];
__device__ float g_ffn [Bsz*Ssz*Fsz];
__device__ float g_d   [Bsz*Tsz*Dsz];
__device__ float g_dq  [Bsz*Tsz*Dsz];
__device__ float g_dtmp[Bsz*Tsz*Dsz];

// ---------------- helpers ----------------
__device__ __forceinline__ float warpSum(float v) {
    #pragma unroll
    for (int o = 16; o; o >>= 1) v += __shfl_xor_sync(0xffffffffu, v, o);
    return v;
}
__device__ __forceinline__ float warpMax(float v) {
    #pragma unroll
    for (int o = 16; o; o >>= 1) v = fmaxf(v, __shfl_xor_sync(0xffffffffu, v, o));
    return v;
}
__device__ __forceinline__ uint4 cvt_tf32x4(float4 v) {
    uint4 u;
    asm("cvt.rna.tf32.f32 %0, %1;" : "=r"(u.x) : "f"(v.x));
    asm("cvt.rna.tf32.f32 %0, %1;" : "=r"(u.y) : "f"(v.y));
    asm("cvt.rna.tf32.f32 %0, %1;" : "=r"(u.z) : "f"(v.z));
    asm("cvt.rna.tf32.f32 %0, %1;" : "=r"(u.w) : "f"(v.w));
    return u;
}
__device__ __forceinline__ float cvt_tf32(float v) {
    uint32_t u;
    asm("cvt.rna.tf32.f32 %0, %1;" : "=r"(u) : "f"(v));
    return __uint_as_float(u);
}
#define MMA_TF32(c, a, b) \
    asm volatile("mma.sync.aligned.m16n8k8.row.col.f32.tf32.tf32.f32 " \
        "{%0,%1,%2,%3}, {%4,%5,%6,%7}, {%8,%9}, {%0,%1,%2,%3};" \
        : "+f"((c)[0]), "+f"((c)[1]), "+f"((c)[2]), "+f"((c)[3]) \
        : "r"((a)[0]), "r"((a)[1]), "r"((a)[2]), "r"((a)[3]), \
          "r"((b)[0]), "r"((b)[1]))
#define MMA_F16(c, a, b) \
    asm volatile("mma.sync.aligned.m16n8k16.row.col.f32.f16.f16.f32 " \
        "{%0,%1,%2,%3}, {%4,%5,%6,%7}, {%8,%9}, {%0,%1,%2,%3};" \
        : "+f"((c)[0]), "+f"((c)[1]), "+f"((c)[2]), "+f"((c)[3]) \
        : "r"((a)[0]), "r"((a)[1]), "r"((a)[2]), "r"((a)[3]), \
          "r"((b)[0]), "r"((b)[1]))

// ---------------- FP16 tensor-core GEMM --------------------------------------------
// C[M,N] = A[M,K] @ B[K,N] + bias[N], opt ReLU. Tile 128x128, BK=32, 256 thr,
// 8 warps (2x4), warp tile 64x32, mma m16n8k16.f16 with fp32 accumulate.
// Smem: As2[kp][m] / Bs2[kp][n] as half2 k-pairs, row stride 136 (conflict-free
// fragment reads: bank = t4*8+g covers all 32).
__device__ __forceinline__ void stA_f16(__half2* __restrict__ dst,
                                        const float4* ra, int akp, int ar)
{
    #pragma unroll
    for (int p = 0; p < 4; p++) {
        dst[(akp + p * 2 + 0) * 136 + ar] = __floats2half2_rn(ra[p].x, ra[p].y);
        dst[(akp + p * 2 + 1) * 136 + ar] = __floats2half2_rn(ra[p].z, ra[p].w);
    }
}
__device__ __forceinline__ void stB_f16(__half2* __restrict__ dst,
                                        const float4* rb, int bkp, int bn0)
{
    __half2 t[8];
    t[0] = __floats2half2_rn(rb[0].x, rb[2].x);
    t[1] = __floats2half2_rn(rb[0].y, rb[2].y);
    t[2] = __floats2half2_rn(rb[0].z, rb[2].z);
    t[3] = __floats2half2_rn(rb[0].w, rb[2].w);
    t[4] = __floats2half2_rn(rb[1].x, rb[3].x);
    t[5] = __floats2half2_rn(rb[1].y, rb[3].y);
    t[6] = __floats2half2_rn(rb[1].z, rb[3].z);
    t[7] = __floats2half2_rn(rb[1].w, rb[3].w);
    *(uint4*)(dst + bkp * 136 + bn0)     = *(uint4*)&t[0];
    *(uint4*)(dst + bkp * 136 + bn0 + 4) = *(uint4*)&t[4];
}

__device__ __forceinline__ void mma_chunk_f16(
    const __half2* __restrict__ Ab, const __half2* __restrict__ Bb,
    int aOff, int bOff, float acc[4][4][4])
{
    #pragma unroll
    for (int kk = 0; kk < 2; kk++) {
        uint32_t af[4][4], bf[4][2];
        #pragma unroll
        for (int mt = 0; mt < 4; mt++) {
            const __half2* a = Ab + kk * 8 * 136 + aOff + mt * 16;
            af[mt][0] = *(const uint32_t*)(a);
            af[mt][1] = *(const uint32_t*)(a + 8);
            af[mt][2] = *(const uint32_t*)(a + 4 * 136);
            af[mt][3] = *(const uint32_t*)(a + 4 * 136 + 8);
        }
        #pragma unroll
        for (int nt = 0; nt < 4; nt++) {
            const __half2* bp = Bb + kk * 8 * 136 + bOff + nt * 8;
            bf[nt][0] = *(const uint32_t*)(bp);
            bf[nt][1] = *(const uint32_t*)(bp + 4 * 136);
        }
        #pragma unroll
        for (int mt = 0; mt < 4; mt++)
            #pragma unroll
            for (int nt = 0; nt < 4; nt++)
                MMA_F16(acc[mt][nt], af[mt], bf[nt]);
    }
}

__global__ __launch_bounds__(256, 2) void gemm_f16(
    const float* __restrict__ A, const float* __restrict__ B,
    const float* __restrict__ bias, float* __restrict__ C,
    int M, int N, int K, int doRelu)
{
    __shared__ __align__(16) __half2 As2[2][16 * 136];
    __shared__ __align__(16) __half2 Bs2[2][16 * 136];

    const int tid = threadIdx.x, lane = tid & 31, warp = tid >> 5;
    const int g = lane >> 2, t4 = lane & 3;
    const int wm = (warp >> 2) << 6, wn = (warp & 3) << 5;
    const int bm = blockIdx.y << 7, bn = blockIdx.x << 7;

    // staging indices
    const int ar  = tid >> 1;            // A row 0..127
    const int akp = (tid & 1) << 3;      // A kpair base 0/8
    const int bkp = tid >> 4;            // B kpair 0..15
    const int bn0 = (tid & 15) << 3;     // B col base (half2 units)

    const float* Ag  = A + (size_t)(bm + ar) * K + (akp << 1);
    const float* Bg0 = B + (size_t)(bkp * 2) * N + bn + bn0;

    // fragment read bases
    const int aOff = t4 * 136 + wm + g;
    const int bOff = t4 * 136 + wn + g;

    float acc[4][4][4] = {};
    float4 ra[4], rb[4];

    // prologue: chunk 0
    #pragma unroll
    for (int p = 0; p < 4; p++) ra[p] = *(const float4*)(Ag + p * 4);
    rb[0] = *(const float4*)(Bg0);
    rb[1] = *(const float4*)(Bg0 + 4);
    rb[2] = *(const float4*)(Bg0 + N);
    rb[3] = *(const float4*)(Bg0 + N + 4);
    stA_f16(As2[0], ra, akp, ar);
    stB_f16(Bs2[0], rb, bkp, bn0);
    __syncthreads();

    int buf = 0;
    for (int k0 = 32; k0 < K; k0 += 32) {
        const float* Agc = Ag + k0;
        const float* Bgc = Bg0 + (size_t)k0 * N;
        #pragma unroll
        for (int p = 0; p < 4; p++) ra[p] = *(const float4*)(Agc + p * 4);
        rb[0] = *(const float4*)(Bgc);
        rb[1] = *(const float4*)(Bgc + 4);
        rb[2] = *(const float4*)(Bgc + N);
        rb[3] = *(const float4*)(Bgc + N + 4);

        mma_chunk_f16(As2[buf], Bs2[buf], aOff, bOff, acc);

        stA_f16(As2[buf ^ 1], ra, akp, ar);
        stB_f16(Bs2[buf ^ 1], rb, bkp, bn0);
        __syncthreads();
        buf ^= 1;
    }
    mma_chunk_f16(As2[buf], Bs2[buf], aOff, bOff, acc);

    // epilogue: bias (+relu), float2 stores
    #pragma unroll
    for (int mt = 0; mt < 4; mt++) {
        const int gm = bm + wm + mt * 16 + g;
        #pragma unroll
        for (int nt = 0; nt < 4; nt++) {
            const int gn = bn + wn + nt * 8 + (t4 << 1);
            const float b0v = bias[gn], b1v = bias[gn + 1];
            float2 o0 = make_float2(acc[mt][nt][0] + b0v, acc[mt][nt][1] + b1v);
            float2 o1 = make_float2(acc[mt][nt][2] + b0v, acc[mt][nt][3] + b1v);
            if (doRelu) {
                o0.x = fmaxf(o0.x, 0.f); o0.y = fmaxf(o0.y, 0.f);
                o1.x = fmaxf(o1.x, 0.f); o1.y = fmaxf(o1.y, 0.f);
            }
            *(float2*)(C + (size_t)gm * N + gn)       = o0;
            *(float2*)(C + (size_t)(gm + 8) * N + gn) = o1;
        }
    }
}

// ---------------- tensor-core flash attention (unchanged, proven) ------------------
#define ATT_SMEM ((4 * 64 * 68 + 192) * 4)
__global__ __launch_bounds__(256) void attn_mma(
    const float* __restrict__ Q, const float* __restrict__ K,
    const float* __restrict__ V, float* __restrict__ O,
    int Sq, int Sk, int causal)
{
    extern __shared__ float sm[];
    float* Qs = sm;
    float* Ks = sm + 4352;
    float* Vs = sm + 8704;
    float* Ss = sm + 13056;
    float* m_row = sm + 17408;
    float* s_row = m_row + 64;
    float* f_row = s_row + 64;

    const int tid = threadIdx.x, lane = tid & 31, w = tid >> 5;
    const int wm = w & 3, wn = w >> 2;
    const int g = lane >> 2, t4 = lane & 3;
    const int qbase = blockIdx.x * 64;
    const int h = blockIdx.y, b = blockIdx.z;
    const size_t hoff = (size_t)h * DHsz;

    #pragma unroll
    for (int p = 0; p < 4; p++) {
        const int row = (tid >> 4) + p * 16;
        const int d4  = (tid & 15) << 2;
        const int qg  = qbase + row;
        float4 v4 = (qg < Sq)
            ? *(const float4*)(Q + (size_t)(b * Sq + qg) * Dsz + hoff + d4)
            : make_float4(0.f, 0.f, 0.f, 0.f);
        *(uint4*)&Qs[row * 68 + d4] = cvt_tf32x4(v4);
    }
    if (tid < 64) { m_row[tid] = -1e30f; s_row[tid] = 0.f; }
    __syncthreads();

    const int qr = wm * 16 + g;
    uint32_t qf[8][4];
    #pragma unroll
    for (int kk = 0; kk < 8; kk++) {
        qf[kk][0] = __float_as_uint(Qs[qr * 68 + kk * 8 + t4]);
        qf[kk][1] = __float_as_uint(Qs[(qr + 8) * 68 + kk * 8 + t4]);
        qf[kk][2] = __float_as_uint(Qs[qr * 68 + kk * 8 + t4 + 4]);
        qf[kk][3] = __float_as_uint(Qs[(qr + 8) * 68 + kk * 8 + t4 + 4]);
    }

    float acc_o[4][4] = {};
    const int qend = qbase + 63;

    for (int c0 = 0; c0 < Sk; c0 += 64) {
        if (causal && c0 > qend) break;
        #pragma unroll
        for (int p = 0; p < 4; p++) {
            const int row = (tid >> 4) + p * 16;
            const int d4  = (tid & 15) << 2;
            const int kg  = c0 + row;
            float4 kv = make_float4(0.f, 0.f, 0.f, 0.f), vv = kv;
            if (kg < Sk) {
                kv = *(const float4*)(K + (size_t)(b * Sk + kg) * Dsz + hoff + d4);
                vv = *(const float4*)(V + (size_t)(b * Sk + kg) * Dsz + hoff + d4);
            }
            *(uint4*)&Ks[row * 68 + d4] = cvt_tf32x4(kv);
            *(uint4*)&Vs[row * 68 + d4] = cvt_tf32x4(vv);
        }
        __syncthreads();

        float acc_s[4][4] = {};
        #pragma unroll
        for (int kk = 0; kk < 8; kk++) {
            #pragma unroll
            for (int nt = 0; nt < 4; nt++) {
                const int key = wn * 32 + nt * 8 + g;
                uint32_t bf[2];
                bf[0] = __float_as_uint(Ks[key * 68 + kk * 8 + t4]);
                bf[1] = __float_as_uint(Ks[key * 68 + kk * 8 + t4 + 4]);
                MMA_TF32(acc_s[nt], qf[kk], bf);
            }
        }
        {
            const int qg0 = qbase + qr, qg1 = qg0 + 8;
            #pragma unroll
            for (int nt = 0; nt < 4; nt++) {
                const int cl = wn * 32 + nt * 8 + (t4 << 1);
                const int kg = c0 + cl;
                float s00 = acc_s[nt][0] * 0.125f, s01 = acc_s[nt][1] * 0.125f;
                float s10 = acc_s[nt][2] * 0.125f, s11 = acc_s[nt][3] * 0.125f;
                if (kg >= Sk || (causal && kg > qg0)) s00 = -1e30f;
                if (kg + 1 >= Sk || (causal && kg + 1 > qg0)) s01 = -1e30f;
                if (kg >= Sk || (causal && kg > qg1)) s10 = -1e30f;
                if (kg + 1 >= Sk || (causal && kg + 1 > qg1)) s11 = -1e30f;
                Ss[qr * 68 + cl] = s00;        Ss[qr * 68 + cl + 1] = s01;
                Ss[(qr + 8) * 68 + cl] = s10;  Ss[(qr + 8) * 68 + cl + 1] = s11;
            }
        }
        __syncthreads();

        #pragma unroll
        for (int rr = 0; rr < 8; rr++) {
            const int r = w * 8 + rr;
            float s0v = Ss[r * 68 + lane];
            float s1v = Ss[r * 68 + lane + 32];
            const float mx = warpMax(fmaxf(s0v, s1v));
            const float mold = m_row[r];
            const float mnew = fmaxf(mold, mx);
            float p0 = __expf(s0v - mnew);
            float p1 = __expf(s1v - mnew);
            const float sum = warpSum(p0 + p1);
            Ss[r * 68 + lane]      = cvt_tf32(p0);
            Ss[r * 68 + lane + 32] = cvt_tf32(p1);
            if (lane == 0) {
                const float f = __expf(mold - mnew);
                f_row[r] = f;
                s_row[r] = s_row[r] * f + sum;
                m_row[r] = mnew;
            }
        }
        __syncthreads();

        {
            const float f0 = f_row[qr], f1 = f_row[qr + 8];
            #pragma unroll
            for (int nt = 0; nt < 4; nt++) {
                acc_o[nt][0] *= f0; acc_o[nt][1] *= f0;
                acc_o[nt][2] *= f1; acc_o[nt][3] *= f1;
            }
        }
        #pragma unroll
        for (int kk = 0; kk < 8; kk++) {
            uint32_t af[4];
            af[0] = __float_as_uint(Ss[qr * 68 + kk * 8 + t4]);
            af[1] = __float_as_uint(Ss[(qr + 8) * 68 + kk * 8 + t4]);
            af[2] = __float_as_uint(Ss[qr * 68 + kk * 8 + t4 + 4]);
            af[3] = __float_as_uint(Ss[(qr + 8) * 68 + kk * 8 + t4 + 4]);
            #pragma unroll
            for (int nt = 0; nt < 4; nt++) {
                const int dcol = wn * 32 + nt * 8 + g;
                uint32_t bf[2];
                bf[0] = __float_as_uint(Vs[(kk * 8 + t4) * 68 + dcol]);
                bf[1] = __float_as_uint(Vs[(kk * 8 + t4 + 4) * 68 + dcol]);
                MMA_TF32(acc_o[nt], af, bf);
            }
        }
        __syncthreads();
    }

    const float inv0 = 1.f / s_row[qr];
    const float inv1 = 1.f / s_row[qr + 8];
    const int qg0 = qbase + qr, qg1 = qg0 + 8;
    #pragma unroll
    for (int nt = 0; nt < 4; nt++) {
        const int dcol = wn * 32 + nt * 8 + (t4 << 1);
        if (qg0 < Sq)
            *(float2*)(O + (size_t)(b * Sq + qg0) * Dsz + hoff + dcol) =
                make_float2(acc_o[nt][0] * inv0, acc_o[nt][1] * inv0);
        if (qg1 < Sq)
            *(float2*)(O + (size_t)(b * Sq + qg1) * Dsz + hoff + dcol) =
                make_float2(acc_o[nt][2] * inv1, acc_o[nt][3] * inv1);
    }
}

// ---------------- residual + LayerNorm ---------------------------------------------
__global__ __launch_bounds__(128) void add_ln_kernel(
    float* __restrict__ h, const float* __restrict__ r,
    const float* __restrict__ scale, const float* __restrict__ bias)
{
    const int row = blockIdx.x;
    const int tid = threadIdx.x;
    const int lane = tid & 31, warp = tid >> 5;
    float* hp = h + (size_t)row * Dsz;
    const float* rp = r + (size_t)row * Dsz;

    float4 hv = *(const float4*)(hp + tid * 4);
    float4 rv = *(const float4*)(rp + tid * 4);
    float v0 = hv.x + rv.x, v1 = hv.y + rv.y, v2 = hv.z + rv.z, v3 = hv.w + rv.w;

    float sum = v0 + v1 + v2 + v3;
    float sq  = v0*v0 + v1*v1 + v2*v2 + v3*v3;
    sum = warpSum(sum); sq = warpSum(sq);

    __shared__ float s1[4], s2[4];
    if (lane == 0) { s1[warp] = sum; s2[warp] = sq; }
    __syncthreads();
    sum = s1[0] + s1[1] + s1[2] + s1[3];
    sq  = s2[0] + s2[1] + s2[2] + s2[3];

    const float mu = sum * (1.f / Dsz);
    const float var = sq * (1.f / Dsz) - mu * mu;
    const float rs = rsqrtf(var + 1e-5f);

    float4 sc4 = *(const float4*)(scale + tid * 4);
    float4 bi4 = *(const float4*)(bias + tid * 4);
    float4 o;
    o.x = (v0 - mu) * rs * sc4.x + bi4.x;
    o.y = (v1 - mu) * rs * sc4.y + bi4.y;
    o.z = (v2 - mu) * rs * sc4.z + bi4.z;
    o.w = (v3 - mu) * rs * sc4.w + bi4.w;
    *(float4*)(hp + tid * 4) = o;
}

// ---------------- embeddings --------------------------------------------------------
__device__ __forceinline__ float pos_enc(int pos, int d) {
    const int i2 = d & ~1;
    const float freq = expf(-(float)i2 * (9.210340371976184f / 512.f));
    const float ang = (float)pos * freq;
    return (d & 1) ? cosf(ang) : sinf(ang);
}
__global__ __launch_bounds__(512) void embed_src_kernel(
    const float* __restrict__ x, const float* __restrict__ w,
    const float* __restrict__ b, float* __restrict__ h)
{
    const int token = blockIdx.x;
    const int d = threadIdx.x;
    const int s = token % Ssz;
    const float x0 = x[token * 2 + 0], x1 = x[token * 2 + 1];
    h[(size_t)token * Dsz + d] = x0 * w[d] + x1 * w[Dsz + d] + b[d] + pos_enc(s, d);
}
__global__ __launch_bounds__(512) void embed_tgt_kernel(
    const float* __restrict__ y, const float* __restrict__ w,
    const float* __restrict__ b, float* __restrict__ dd)
{
    const int token = blockIdx.x;
    const int d = threadIdx.x;
    const int bb = token / Tsz, t = token % Tsz;
    const float val = (t == 0) ? 0.f : y[bb * Tsz + (t - 1)];
    dd[(size_t)token * Dsz + d] = val * w[d] + b[d] + pos_enc(t, d);
}

// ---------------- final projection ---------------------------------------------------
__global__ __launch_bounds__(128) void out_proj_kernel(
    const float* __restrict__ dd, const float* __restrict__ w,
    const float* __restrict__ b, float* __restrict__ out)
{
    const int token = blockIdx.x;
    const int tid = threadIdx.x;
    const int lane = tid & 31, warp = tid >> 5;
    float s = 0.f;
    for (int i = tid; i < Dsz; i += 128)
        s += dd[(size_t)token * Dsz + i] * w[i];
    s = warpSum(s);
    __shared__ float smr[4];
    if (lane == 0) smr[warp] = s;
    __syncthreads();
    if (tid == 0) out[token] = smr[0] + smr[1] + smr[2] + smr[3] + b[0];
}

// ---------------- host orchestration -------------------------------------------------
extern "C" void kernel_launch(void* const* d_in, const int* in_sizes, int n_in,
                              void* d_out, int out_size)
{
    const float* x          = (const float*)d_in[0];
    const float* y          = (const float*)d_in[1];
    const float* src_w      = (const float*)d_in[2];
    const float* src_b      = (const float*)d_in[3];
    const float* tgt_w      = (const float*)d_in[4];
    const float* tgt_b      = (const float*)d_in[5];
    const float* enc_attn_w = (const float*)d_in[6];
    const float* enc_attn_b = (const float*)d_in[7];
    const float* enc_ffn_w1 = (const float*)d_in[8];
    const float* enc_ffn_b1 = (const float*)d_in[9];
    const float* enc_ffn_w2 = (const float*)d_in[10];
    const float* enc_ffn_b2 = (const float*)d_in[11];
    const float* enc_ln_s   = (const float*)d_in[12];
    const float* enc_ln_b   = (const float*)d_in[13];
    const float* dec_self_w = (const float*)d_in[14];
    const float* dec_self_b = (const float*)d_in[15];
    const float* dec_cross_w= (const float*)d_in[16];
    const float* dec_cross_b= (const float*)d_in[17];
    const float* dec_ffn_w1 = (const float*)d_in[18];
    const float* dec_ffn_b1 = (const float*)d_in[19];
    const float* dec_ffn_w2 = (const float*)d_in[20];
    const float* dec_ffn_b2 = (const float*)d_in[21];
    const float* dec_ln_s   = (const float*)d_in[22];
    const float* dec_ln_b   = (const float*)d_in[23];
    const float* out_w      = (const float*)d_in[24];
    const float* out_b      = (const float*)d_in[25];

    float *h, *tmp, *q, *k, *v, *ffn, *dd, *dq, *dtmp;
    cudaGetSymbolAddress((void**)&h,    g_h);
    cudaGetSymbolAddress((void**)&tmp,  g_tmp);
    cudaGetSymbolAddress((void**)&q,    g_q);
    cudaGetSymbolAddress((void**)&k,    g_k);
    cudaGetSymbolAddress((void**)&v,    g_v);
    cudaGetSymbolAddress((void**)&ffn,  g_ffn);
    cudaGetSymbolAddress((void**)&dd,   g_d);
    cudaGetSymbolAddress((void**)&dq,   g_dq);
    cudaGetSymbolAddress((void**)&dtmp, g_dtmp);

    const int Me = Bsz * Ssz;   // 16384
    const int Md = Bsz * Tsz;   // 5760
    const size_t DD = (size_t)Dsz * Dsz;

    cudaFuncSetAttribute(attn_mma, cudaFuncAttributeMaxDynamicSharedMemorySize, ATT_SMEM);
    const int qtE = Ssz / 64;                 // 8
    const int qtD = (Tsz + 63) / 64;          // 3

    dim3 blk(256);
    dim3 gE_D(Dsz / 128, Me / 128);
    dim3 gE_F(Fsz / 128, Me / 128);
    dim3 gD_D(Dsz / 128, Md / 128);
    dim3 gD_F(Fsz / 128, Md / 128);

    // ===== encoder =====
    embed_src_kernel<<<Me, 512>>>(x, src_w, src_b, h);
    for (int l = 0; l < Lsz; l++) {
        const float* w  = enc_attn_w + (size_t)l * 4 * DD;
        const float* wb = enc_attn_b + (size_t)l * 4 * Dsz;
        gemm_f16<<<gE_D, blk>>>(h, w,          wb,          q, Me, Dsz, Dsz, 0);
        gemm_f16<<<gE_D, blk>>>(h, w + DD,     wb + Dsz,    k, Me, Dsz, Dsz, 0);
        gemm_f16<<<gE_D, blk>>>(h, w + 2*DD,   wb + 2*Dsz,  v, Me, Dsz, Dsz, 0);
        attn_mma<<<dim3(qtE, Hsz, Bsz), 256, ATT_SMEM>>>(q, k, v, tmp, Ssz, Ssz, 0);
        gemm_f16<<<gE_D, blk>>>(tmp, w + 3*DD, wb + 3*Dsz,  q, Me, Dsz, Dsz, 0);
        add_ln_kernel<<<Me, 128>>>(h, q, enc_ln_s + (size_t)(l*2)*Dsz,
                                         enc_ln_b + (size_t)(l*2)*Dsz);
        gemm_f16<<<gE_F, blk>>>(h, enc_ffn_w1 + (size_t)l*Dsz*Fsz,
                                enc_ffn_b1 + (size_t)l*Fsz, ffn, Me, Fsz, Dsz, 1);
        gemm_f16<<<gE_D, blk>>>(ffn, enc_ffn_w2 + (size_t)l*Fsz*Dsz,
                                enc_ffn_b2 + (size_t)l*Dsz, tmp, Me, Dsz, Fsz, 0);
        add_ln_kernel<<<Me, 128>>>(h, tmp, enc_ln_s + (size_t)(l*2+1)*Dsz,
                                           enc_ln_b + (size_t)(l*2+1)*Dsz);
    }

    // ===== decoder =====
    embed_tgt_kernel<<<Md, 512>>>(y, tgt_w, tgt_b, dd);
    for (int l = 0; l < Lsz; l++) {
        const float* w  = dec_self_w + (size_t)l * 4 * DD;
        const float* wb = dec_self_b + (size_t)l * 4 * Dsz;
        gemm_f16<<<gD_D, blk>>>(dd, w,        wb,         dq, Md, Dsz, Dsz, 0);
        gemm_f16<<<gD_D, blk>>>(dd, w + DD,   wb + Dsz,   k,  Md, Dsz, Dsz, 0);
        gemm_f16<<<gD_D, blk>>>(dd, w + 2*DD, wb + 2*Dsz, v,  Md, Dsz, Dsz, 0);
        attn_mma<<<dim3(qtD, Hsz, Bsz), 256, ATT_SMEM>>>(dq, k, v, dtmp, Tsz, Tsz, 1);
        gemm_f16<<<gD_D, blk>>>(dtmp, w + 3*DD, wb + 3*Dsz, dq, Md, Dsz, Dsz, 0);
        add_ln_kernel<<<Md, 128>>>(dd, dq, dec_ln_s + (size_t)(l*3)*Dsz,
                                           dec_ln_b + (size_t)(l*3)*Dsz);

        const float* cw  = dec_cross_w + (size_t)l * 4 * DD;
        const float* cwb = dec_cross_b + (size_t)l * 4 * Dsz;
        gemm_f16<<<gD_D, blk>>>(dd, cw,        cwb,         dq, Md, Dsz, Dsz, 0);
        gemm_f16<<<gE_D, blk>>>(h,  cw + DD,   cwb + Dsz,   k,  Me, Dsz, Dsz, 0);
        gemm_f16<<<gE_D, blk>>>(h,  cw + 2*DD, cwb + 2*Dsz, v,  Me, Dsz, Dsz, 0);
        attn_mma<<<dim3(qtD, Hsz, Bsz), 256, ATT_SMEM>>>(dq, k, v, dtmp, Tsz, Ssz, 0);
        gemm_f16<<<gD_D, blk>>>(dtmp, cw + 3*DD, cwb + 3*Dsz, dq, Md, Dsz, Dsz, 0);
        add_ln_kernel<<<Md, 128>>>(dd, dq, dec_ln_s + (size_t)(l*3+1)*Dsz,
                                           dec_ln_b + (size_t)(l*3+1)*Dsz);

        gemm_f16<<<gD_F, blk>>>(dd, dec_ffn_w1 + (size_t)l*Dsz*Fsz,
                                dec_ffn_b1 + (size_t)l*Fsz, ffn, Md, Fsz, Dsz, 1);
        gemm_f16<<<gD_D, blk>>>(ffn, dec_ffn_w2 + (size_t)l*Fsz*Dsz,
                                dec_ffn_b2 + (size_t)l*Dsz, dtmp, Md, Dsz, Fsz, 0);
        add_ln_kernel<<<Md, 128>>>(dd, dtmp, dec_ln_s + (size_t)(l*3+2)*Dsz,
                                             dec_ln_b + (size_t)(l*3+2)*Dsz);
    }

    out_proj_kernel<<<Md, 128>>>(dd, out_w, out_b, (float*)d_out);
}